// round 4
// baseline (speedup 1.0000x reference)
#include <cuda_runtime.h>

#define NN 100000
#define NE 1600000
#define NG 1000

// ---------------- scratch (device globals; 16B-aligned) --------------------
__device__ __align__(16) float g_Z[NN * 64];
__device__ __align__(16) float g_Pa[NN * 64];
__device__ __align__(16) float g_Pb[NN * 64];
__device__ int g_deg[NN];
__device__ int g_rowstart[NN];
__device__ int g_cursor[NN];
__device__ int g_srclist[NE];

// compile-time buffer selection (0 = external input, 1 = g_Pa, 2 = g_Pb)
template <int SEL> __device__ __forceinline__ const float* in_buf(const float* ext);
template <> __device__ __forceinline__ const float* in_buf<0>(const float* ext) { return ext; }
template <> __device__ __forceinline__ const float* in_buf<1>(const float*) { return g_Pa; }
template <> __device__ __forceinline__ const float* in_buf<2>(const float*) { return g_Pb; }
template <int SEL> __device__ __forceinline__ float* out_buf();
template <> __device__ __forceinline__ float* out_buf<1>() { return g_Pa; }
template <> __device__ __forceinline__ float* out_buf<2>() { return g_Pb; }

// ---------------- CSR build (edge_index is int32: JAX x64 disabled) --------
__global__ void zero_deg_kernel() {
    int i = blockIdx.x * 256 + threadIdx.x;
    if (i < NN) g_deg[i] = 0;
}

__global__ void count_deg_kernel(const int* __restrict__ ei) {
    int e = blockIdx.x * 256 + threadIdx.x;
    if (e >= NE) return;
    int d = ei[NE + e];                    // dst row of edge_index
    if ((unsigned)d < NN) atomicAdd(&g_deg[d], 1);
}

// single-block exclusive scan over NN degrees -> rowstart, cursor
__global__ void __launch_bounds__(1024) scan_kernel() {
    __shared__ int part[1024];
    const int CH = (NN + 1023) / 1024;  // 98
    int t = threadIdx.x;
    int lo = t * CH, hi = min(lo + CH, NN);
    int s = 0;
    for (int i = lo; i < hi; i++) s += g_deg[i];
    part[t] = s;
    __syncthreads();
    for (int off = 1; off < 1024; off <<= 1) {
        int v = part[t];
        int u = (t >= off) ? part[t - off] : 0;
        __syncthreads();
        part[t] = v + u;
        __syncthreads();
    }
    int run = (t == 0) ? 0 : part[t - 1];  // exclusive prefix
    for (int i = lo; i < hi; i++) {
        g_rowstart[i] = run;
        g_cursor[i] = run;
        run += g_deg[i];
    }
}

__global__ void fill_csr_kernel(const int* __restrict__ ei) {
    int e = blockIdx.x * 256 + threadIdx.x;
    if (e >= NE) return;
    int s = ei[e];
    int d = ei[NE + e];
    if ((unsigned)s >= NN || (unsigned)d >= NN) return;
    int pos = atomicAdd(&g_cursor[d], 1);
    if ((unsigned)pos < NE) g_srclist[pos] = s;
}

// ---------------- GEMM: Z = (relu?)(A) @ W, row-per-thread -----------------
// W staged in shared (float4-typed -> 16B aligned). Inner j-loop is
// warp-uniform -> conflict-free LDS broadcasts.
template <int K, bool RELU_IN, int IN_SEL>
__global__ void __launch_bounds__(256) gemm64_kernel(
    const float* ext_A, const float* __restrict__ W)
{
    __shared__ float4 Ws4[K * 16];   // K rows x 64 cols
    for (int i = threadIdx.x; i < K * 16; i += 256) {
        const float* wp = W + i * 4;
        Ws4[i] = make_float4(wp[0], wp[1], wp[2], wp[3]);
    }
    __syncthreads();

    const float* A = in_buf<IN_SEL>(ext_A);
    int row = blockIdx.x * 256 + threadIdx.x;
    if (row >= NN) return;

    float acc[64];
#pragma unroll
    for (int j = 0; j < 64; j++) acc[j] = 0.0f;

    const float4* A4 = (const float4*)(A + (long long)row * K);
#pragma unroll 1
    for (int k4 = 0; k4 < K / 4; k4++) {
        float4 a = A4[k4];
        if (RELU_IN) {
            a.x = fmaxf(a.x, 0.0f); a.y = fmaxf(a.y, 0.0f);
            a.z = fmaxf(a.z, 0.0f); a.w = fmaxf(a.w, 0.0f);
        }
        const float av[4] = {a.x, a.y, a.z, a.w};
#pragma unroll
        for (int kk = 0; kk < 4; kk++) {
            const float4* wr = &Ws4[(k4 * 4 + kk) * 16];
            float m = av[kk];
#pragma unroll
            for (int j4 = 0; j4 < 16; j4++) {
                float4 w = wr[j4];
                acc[4 * j4 + 0] = fmaf(m, w.x, acc[4 * j4 + 0]);
                acc[4 * j4 + 1] = fmaf(m, w.y, acc[4 * j4 + 1]);
                acc[4 * j4 + 2] = fmaf(m, w.z, acc[4 * j4 + 2]);
                acc[4 * j4 + 3] = fmaf(m, w.w, acc[4 * j4 + 3]);
            }
        }
    }

    float4* Z4 = (float4*)(g_Z + (long long)row * 64);
#pragma unroll
    for (int j4 = 0; j4 < 16; j4++)
        Z4[j4] = make_float4(acc[4 * j4], acc[4 * j4 + 1],
                             acc[4 * j4 + 2], acc[4 * j4 + 3]);
}

// ---------------- gather: P[n] = (1+eps)*Z[n] + b + sum_in Z[src] ----------
// 16 threads per node; each thread owns one float4 lane of the 64-dim row.
template <int OUT_SEL>
__global__ void __launch_bounds__(256) gather_kernel(
    const float* __restrict__ b, const float* __restrict__ epsp)
{
    int gid = blockIdx.x * 256 + threadIdx.x;
    int n = gid >> 4;
    int lane = gid & 15;
    if (n >= NN) return;

    const float4* Z4 = (const float4*)g_Z;
    float ep = 1.0f + *epsp;
    const float* bp = b + lane * 4;   // scalar loads: no alignment assumption

    float4 z = Z4[n * 16 + lane];
    float4 acc;
    acc.x = fmaf(ep, z.x, bp[0]);
    acc.y = fmaf(ep, z.y, bp[1]);
    acc.z = fmaf(ep, z.z, bp[2]);
    acc.w = fmaf(ep, z.w, bp[3]);

    int beg = g_rowstart[n];
    int end = beg + g_deg[n];
    for (int k = beg; k < end; k++) {
        int s = g_srclist[k];
        float4 v = Z4[s * 16 + lane];
        acc.x += v.x; acc.y += v.y; acc.z += v.z; acc.w += v.w;
    }

    float4* P4 = (float4*)out_buf<OUT_SEL>();
    P4[n * 16 + lane] = acc;
}

// ---------------- pool (batch is sorted int32) + MLP head ------------------
__global__ void __launch_bounds__(64) pool_head_kernel(
    const int* __restrict__ batch,
    const float* __restrict__ Wf, const float* __restrict__ bf,
    const float* __restrict__ Wl, const float* __restrict__ bl,
    float* __restrict__ out)
{
    int g = blockIdx.x;
    int t = threadIdx.x;

    // node range of graph g: [lower_bound(g), lower_bound(g+1))
    int lo = 0, hi = NN;
    while (lo < hi) { int m = (lo + hi) >> 1; if (batch[m] < g) lo = m + 1; else hi = m; }
    int beg = lo;
    lo = beg; hi = NN;
    while (lo < hi) { int m = (lo + hi) >> 1; if (batch[m] < g + 1) lo = m + 1; else hi = m; }
    int end = lo;

    float s = 0.0f;
    for (int n = beg; n < end; n++)
        s += fmaxf(g_Pa[(long long)n * 64 + t], 0.0f);
    float cnt = (float)(end - beg);
    float pooled = s / fmaxf(cnt, 1.0f);

    __shared__ float ps[64];
    __shared__ float ts[10];
    ps[t] = pooled;
    __syncthreads();

    if (t < 10) {
        float acc = bf[t];
        for (int j = 0; j < 64; j++)
            acc = fmaf(ps[j], Wf[j * 10 + t], acc);
        ts[t] = fmaxf(acc, 0.0f);
    }
    __syncthreads();

    if (t == 0) {
        float r = bl[0];
#pragma unroll
        for (int o = 0; o < 10; o++) r = fmaf(ts[o], Wl[o], r);
        out[g] = r;
    }
}

// ---------------- launch ---------------------------------------------------
extern "C" void kernel_launch(void* const* d_in, const int* in_sizes, int n_in,
                              void* d_out, int out_size)
{
    const float* x     = (const float*)d_in[0];
    const int*   ei    = (const int*)d_in[1];     // int32 (JAX x64 disabled)
    const int*   batch = (const int*)d_in[2];     // int32, sorted
    const float* W1 = (const float*)d_in[3];
    const float* b1 = (const float*)d_in[4];
    const float* W2 = (const float*)d_in[5];
    const float* b2 = (const float*)d_in[6];
    const float* W3 = (const float*)d_in[7];
    const float* b3 = (const float*)d_in[8];
    const float* Wf = (const float*)d_in[9];
    const float* bf = (const float*)d_in[10];
    const float* Wl = (const float*)d_in[11];
    const float* bl = (const float*)d_in[12];
    const float* e1 = (const float*)d_in[13];
    const float* e2 = (const float*)d_in[14];
    const float* e3 = (const float*)d_in[15];
    float* out = (float*)d_out;

    const int node_grid = (NN + 255) / 256;      // 391
    const int edge_grid = (NE + 255) / 256;      // 6250
    const int gath_grid = (NN * 16 + 255) / 256; // 6250

    // CSR by destination (reused for all 3 layers)
    zero_deg_kernel<<<node_grid, 256>>>();
    count_deg_kernel<<<edge_grid, 256>>>(ei);
    scan_kernel<<<1, 1024>>>();
    fill_csr_kernel<<<edge_grid, 256>>>(ei);

    // Layer 1: Z = x@W1 ; Pa = (1+e1)Z + b1 + gather(Z)
    gemm64_kernel<128, false, 0><<<node_grid, 256>>>(x, W1);
    gather_kernel<1><<<gath_grid, 256>>>(b1, e1);

    // Layer 2: Z = relu(Pa)@W2 ; Pb = (1+e2)Z + b2 + gather(Z)
    gemm64_kernel<64, true, 1><<<node_grid, 256>>>(nullptr, W2);
    gather_kernel<2><<<gath_grid, 256>>>(b2, e2);

    // Layer 3: Z = relu(Pb)@W3 ; Pa = (1+e3)Z + b3 + gather(Z)
    gemm64_kernel<64, true, 2><<<node_grid, 256>>>(nullptr, W3);
    gather_kernel<1><<<gath_grid, 256>>>(b3, e3);

    // Mean-pool relu(Pa) per graph + head MLP
    pool_head_kernel<<<NG, 64>>>(batch, Wf, bf, Wl, bl, out);
}

// round 5
// speedup vs baseline: 1.4922x; 1.4922x over previous
#include <cuda_runtime.h>

#define NN 100000
#define NE 1600000
#define NG 1000
#define NB 98              // scan blocks: 98 * 1024 >= NN

// ---------------- scratch (device globals; 16B-aligned) --------------------
__device__ __align__(16) float g_Z[NN * 64];
__device__ __align__(16) float g_Pa[NN * 64];
__device__ __align__(16) float g_Pb[NN * 64];
__device__ __align__(16) int g_deg[NN];
__device__ int g_rowstart[NN];
__device__ int g_cursor[NN];
__device__ int g_srclist[NE];
__device__ int g_bsum[128];
__device__ int g_boff[128];

// compile-time buffer selection (0 = external input, 1 = g_Pa, 2 = g_Pb)
template <int SEL> __device__ __forceinline__ const float* in_buf(const float* ext);
template <> __device__ __forceinline__ const float* in_buf<0>(const float* ext) { return ext; }
template <> __device__ __forceinline__ const float* in_buf<1>(const float*) { return g_Pa; }
template <> __device__ __forceinline__ const float* in_buf<2>(const float*) { return g_Pb; }
template <int SEL> __device__ __forceinline__ float* out_buf();
template <> __device__ __forceinline__ float* out_buf<1>() { return g_Pa; }
template <> __device__ __forceinline__ float* out_buf<2>() { return g_Pb; }

// ---------------- CSR build (edge_index is int32) --------------------------
__global__ void zero_deg_kernel() {
    int i = blockIdx.x * 256 + threadIdx.x;
    if (i < NN) g_deg[i] = 0;
}

// 4 edges per thread, loads hoisted -> 4 atomics in flight
__global__ void __launch_bounds__(256) count_deg_kernel(const int* __restrict__ ei) {
    int t = blockIdx.x * 256 + threadIdx.x;
    int d0 = -1, d1 = -1, d2 = -1, d3 = -1;
    int e0 = t * 4;
    if (e0 + 3 < NE) {
        d0 = ei[NE + e0]; d1 = ei[NE + e0 + 1];
        d2 = ei[NE + e0 + 2]; d3 = ei[NE + e0 + 3];
    } else {
        if (e0 < NE)     d0 = ei[NE + e0];
        if (e0 + 1 < NE) d1 = ei[NE + e0 + 1];
        if (e0 + 2 < NE) d2 = ei[NE + e0 + 2];
        if (e0 + 3 < NE) d3 = ei[NE + e0 + 3];
    }
    if ((unsigned)d0 < NN) atomicAdd(&g_deg[d0], 1);
    if ((unsigned)d1 < NN) atomicAdd(&g_deg[d1], 1);
    if ((unsigned)d2 < NN) atomicAdd(&g_deg[d2], 1);
    if ((unsigned)d3 < NN) atomicAdd(&g_deg[d3], 1);
}

// --- 3-phase multi-block exclusive scan: deg -> rowstart/cursor ------------
// Phase A: per-block (1024 elems) sums
__global__ void __launch_bounds__(256) scanA_kernel() {
    __shared__ int red[256];
    int t = threadIdx.x;
    int base = blockIdx.x * 1024 + t * 4;
    int s = 0;
#pragma unroll
    for (int i = 0; i < 4; i++) {
        int idx = base + i;
        if (idx < NN) s += g_deg[idx];
    }
    red[t] = s;
    __syncthreads();
    for (int off = 128; off > 0; off >>= 1) {
        if (t < off) red[t] += red[t + off];
        __syncthreads();
    }
    if (t == 0) g_bsum[blockIdx.x] = red[0];
}

// Phase B: exclusive scan of NB block sums (tiny, 1 block)
__global__ void __launch_bounds__(128) scanB_kernel() {
    __shared__ int sh[128];
    int t = threadIdx.x;
    sh[t] = (t < NB) ? g_bsum[t] : 0;
    __syncthreads();
    for (int off = 1; off < 128; off <<= 1) {
        int v = sh[t];
        int u = (t >= off) ? sh[t - off] : 0;
        __syncthreads();
        sh[t] = v + u;
        __syncthreads();
    }
    if (t < NB) g_boff[t] = (t == 0) ? 0 : sh[t - 1];
}

// Phase C: local prefix within block + offset -> rowstart, cursor
__global__ void __launch_bounds__(256) scanC_kernel() {
    __shared__ int sh[256];
    int t = threadIdx.x;
    int base = blockIdx.x * 1024 + t * 4;
    int d[4];
    int s = 0;
#pragma unroll
    for (int i = 0; i < 4; i++) {
        int idx = base + i;
        d[i] = (idx < NN) ? g_deg[idx] : 0;
        s += d[i];
    }
    sh[t] = s;
    __syncthreads();
    for (int off = 1; off < 256; off <<= 1) {
        int v = sh[t];
        int u = (t >= off) ? sh[t - off] : 0;
        __syncthreads();
        sh[t] = v + u;
        __syncthreads();
    }
    int run = g_boff[blockIdx.x] + ((t == 0) ? 0 : sh[t - 1]);
#pragma unroll
    for (int i = 0; i < 4; i++) {
        int idx = base + i;
        if (idx < NN) {
            g_rowstart[idx] = run;
            g_cursor[idx] = run;
            run += d[i];
        }
    }
}

// 4 edges per thread, index loads hoisted
__global__ void __launch_bounds__(256) fill_csr_kernel(const int* __restrict__ ei) {
    int t = blockIdx.x * 256 + threadIdx.x;
    int e0 = t * 4;
    int s[4], d[4];
#pragma unroll
    for (int i = 0; i < 4; i++) {
        int e = e0 + i;
        bool ok = e < NE;
        s[i] = ok ? ei[e] : -1;
        d[i] = ok ? ei[NE + e] : -1;
    }
#pragma unroll
    for (int i = 0; i < 4; i++) {
        if ((unsigned)s[i] < NN && (unsigned)d[i] < NN) {
            int pos = atomicAdd(&g_cursor[d[i]], 1);
            if ((unsigned)pos < NE) g_srclist[pos] = s[i];
        }
    }
}

// ---------------- GEMM: Z = (relu?)(A) @ W, row-per-thread -----------------
template <int K, bool RELU_IN, int IN_SEL>
__global__ void __launch_bounds__(256) gemm64_kernel(
    const float* ext_A, const float* __restrict__ W)
{
    __shared__ float4 Ws4[K * 16];   // K rows x 64 cols
    for (int i = threadIdx.x; i < K * 16; i += 256) {
        const float* wp = W + i * 4;
        Ws4[i] = make_float4(wp[0], wp[1], wp[2], wp[3]);
    }
    __syncthreads();

    const float* A = in_buf<IN_SEL>(ext_A);
    int row = blockIdx.x * 256 + threadIdx.x;
    if (row >= NN) return;

    float acc[64];
#pragma unroll
    for (int j = 0; j < 64; j++) acc[j] = 0.0f;

    const float4* A4 = (const float4*)(A + (long long)row * K);
#pragma unroll 1
    for (int k4 = 0; k4 < K / 4; k4++) {
        float4 a = A4[k4];
        if (RELU_IN) {
            a.x = fmaxf(a.x, 0.0f); a.y = fmaxf(a.y, 0.0f);
            a.z = fmaxf(a.z, 0.0f); a.w = fmaxf(a.w, 0.0f);
        }
        const float av[4] = {a.x, a.y, a.z, a.w};
#pragma unroll
        for (int kk = 0; kk < 4; kk++) {
            const float4* wr = &Ws4[(k4 * 4 + kk) * 16];
            float m = av[kk];
#pragma unroll
            for (int j4 = 0; j4 < 16; j4++) {
                float4 w = wr[j4];
                acc[4 * j4 + 0] = fmaf(m, w.x, acc[4 * j4 + 0]);
                acc[4 * j4 + 1] = fmaf(m, w.y, acc[4 * j4 + 1]);
                acc[4 * j4 + 2] = fmaf(m, w.z, acc[4 * j4 + 2]);
                acc[4 * j4 + 3] = fmaf(m, w.w, acc[4 * j4 + 3]);
            }
        }
    }

    float4* Z4 = (float4*)(g_Z + (long long)row * 64);
#pragma unroll
    for (int j4 = 0; j4 < 16; j4++)
        Z4[j4] = make_float4(acc[4 * j4], acc[4 * j4 + 1],
                             acc[4 * j4 + 2], acc[4 * j4 + 3]);
}

// ---------------- gather: P[n] = (1+eps)*Z[n] + b + sum_in Z[src] ----------
// 16 threads per node, float4 lane each; unroll-4 for 4 gathers in flight.
template <int OUT_SEL>
__global__ void __launch_bounds__(256) gather_kernel(
    const float* __restrict__ b, const float* __restrict__ epsp)
{
    int gid = blockIdx.x * 256 + threadIdx.x;
    int n = gid >> 4;
    int lane = gid & 15;
    if (n >= NN) return;

    const float4* Z4 = (const float4*)g_Z;
    float ep = 1.0f + *epsp;
    const float* bp = b + lane * 4;

    float4 z = Z4[n * 16 + lane];
    float4 acc;
    acc.x = fmaf(ep, z.x, bp[0]);
    acc.y = fmaf(ep, z.y, bp[1]);
    acc.z = fmaf(ep, z.z, bp[2]);
    acc.w = fmaf(ep, z.w, bp[3]);

    int beg = g_rowstart[n];
    int end = beg + g_deg[n];
    int k = beg;
    for (; k + 4 <= end; k += 4) {
        int s0 = g_srclist[k];
        int s1 = g_srclist[k + 1];
        int s2 = g_srclist[k + 2];
        int s3 = g_srclist[k + 3];
        float4 v0 = Z4[s0 * 16 + lane];
        float4 v1 = Z4[s1 * 16 + lane];
        float4 v2 = Z4[s2 * 16 + lane];
        float4 v3 = Z4[s3 * 16 + lane];
        acc.x += v0.x + v1.x + v2.x + v3.x;
        acc.y += v0.y + v1.y + v2.y + v3.y;
        acc.z += v0.z + v1.z + v2.z + v3.z;
        acc.w += v0.w + v1.w + v2.w + v3.w;
    }
    for (; k < end; k++) {
        int s = g_srclist[k];
        float4 v = Z4[s * 16 + lane];
        acc.x += v.x; acc.y += v.y; acc.z += v.z; acc.w += v.w;
    }

    float4* P4 = (float4*)out_buf<OUT_SEL>();
    P4[n * 16 + lane] = acc;
}

// ---------------- pool (batch sorted int32) + MLP head ---------------------
__global__ void __launch_bounds__(64) pool_head_kernel(
    const int* __restrict__ batch,
    const float* __restrict__ Wf, const float* __restrict__ bf,
    const float* __restrict__ Wl, const float* __restrict__ bl,
    float* __restrict__ out)
{
    int g = blockIdx.x;
    int t = threadIdx.x;

    int lo = 0, hi = NN;
    while (lo < hi) { int m = (lo + hi) >> 1; if (batch[m] < g) lo = m + 1; else hi = m; }
    int beg = lo;
    lo = beg; hi = NN;
    while (lo < hi) { int m = (lo + hi) >> 1; if (batch[m] < g + 1) lo = m + 1; else hi = m; }
    int end = lo;

    float s = 0.0f;
    for (int n = beg; n < end; n++)
        s += fmaxf(g_Pa[(long long)n * 64 + t], 0.0f);
    float cnt = (float)(end - beg);
    float pooled = s / fmaxf(cnt, 1.0f);

    __shared__ float ps[64];
    __shared__ float ts[10];
    ps[t] = pooled;
    __syncthreads();

    if (t < 10) {
        float acc = bf[t];
        for (int j = 0; j < 64; j++)
            acc = fmaf(ps[j], Wf[j * 10 + t], acc);
        ts[t] = fmaxf(acc, 0.0f);
    }
    __syncthreads();

    if (t == 0) {
        float r = bl[0];
#pragma unroll
        for (int o = 0; o < 10; o++) r = fmaf(ts[o], Wl[o], r);
        out[g] = r;
    }
}

// ---------------- launch ---------------------------------------------------
extern "C" void kernel_launch(void* const* d_in, const int* in_sizes, int n_in,
                              void* d_out, int out_size)
{
    const float* x     = (const float*)d_in[0];
    const int*   ei    = (const int*)d_in[1];     // int32 (JAX x64 disabled)
    const int*   batch = (const int*)d_in[2];     // int32, sorted
    const float* W1 = (const float*)d_in[3];
    const float* b1 = (const float*)d_in[4];
    const float* W2 = (const float*)d_in[5];
    const float* b2 = (const float*)d_in[6];
    const float* W3 = (const float*)d_in[7];
    const float* b3 = (const float*)d_in[8];
    const float* Wf = (const float*)d_in[9];
    const float* bf = (const float*)d_in[10];
    const float* Wl = (const float*)d_in[11];
    const float* bl = (const float*)d_in[12];
    const float* e1 = (const float*)d_in[13];
    const float* e2 = (const float*)d_in[14];
    const float* e3 = (const float*)d_in[15];
    float* out = (float*)d_out;

    const int node_grid  = (NN + 255) / 256;           // 391
    const int edge4_grid = (NE + 1023) / 1024;         // 1563
    const int gath_grid  = (NN * 16 + 255) / 256;      // 6250

    // CSR by destination (reused for all 3 layers)
    zero_deg_kernel<<<node_grid, 256>>>();
    count_deg_kernel<<<edge4_grid, 256>>>(ei);
    scanA_kernel<<<NB, 256>>>();
    scanB_kernel<<<1, 128>>>();
    scanC_kernel<<<NB, 256>>>();
    fill_csr_kernel<<<edge4_grid, 256>>>(ei);

    // Layer 1: Z = x@W1 ; Pa = (1+e1)Z + b1 + gather(Z)
    gemm64_kernel<128, false, 0><<<node_grid, 256>>>(x, W1);
    gather_kernel<1><<<gath_grid, 256>>>(b1, e1);

    // Layer 2: Z = relu(Pa)@W2 ; Pb = (1+e2)Z + b2 + gather(Z)
    gemm64_kernel<64, true, 1><<<node_grid, 256>>>(nullptr, W2);
    gather_kernel<2><<<gath_grid, 256>>>(b2, e2);

    // Layer 3: Z = relu(Pb)@W3 ; Pa = (1+e3)Z + b3 + gather(Z)
    gemm64_kernel<64, true, 2><<<node_grid, 256>>>(nullptr, W3);
    gather_kernel<1><<<gath_grid, 256>>>(b3, e3);

    // Mean-pool relu(Pa) per graph + head MLP
    pool_head_kernel<<<NG, 64>>>(batch, Wf, bf, Wl, bl, out);
}